// round 15
// baseline (speedup 1.0000x reference)
#include <cuda_runtime.h>
#include <math.h>

#define NL 4
#define H  1024
#define E  2048
#define G3 3072
#define OUTN 50257

// Persistent scratch (__device__ globals; no allocation allowed).
__device__ float g_x[E];          // current layer input (E = 2H)
__device__ float g_gi[2 * G3];    // W_ih @ x + b_ih  (current layer)
__device__ float g_gh[2 * G3];    // W_hh @ h + b_hh  (current layer)

__device__ __forceinline__ float sigmoidf(float x) {
    return 1.0f / (1.0f + expf(-x));
}

__device__ __forceinline__ void pdl_wait() {
    asm volatile("griddepcontrol.wait;" ::: "memory");
}

// ---------------------------------------------------------------------------
// Gates: ONE 64-thread block per output row (grid = 6144).
// Deep front batch: 8 float4 from W_ih + 8 from x per thread (8 outstanding
// DRAM lines per warp), minimal 2-warp reduce tail.  W_hh loads (4 float4)
// are issued only if the row's h-slice is nonzero (deterministic skip — the
// problem's hidden input is structurally zero; general path stays correct).
// ---------------------------------------------------------------------------
__global__ void __launch_bounds__(64) gates_kernel(
    const float* __restrict__ wih, const float* __restrict__ whh,
    const float* __restrict__ bih, const float* __restrict__ bhh,
    const float* __restrict__ hidden, const float* __restrict__ table,
    const int* __restrict__ feat, int l) {

    pdl_wait();

    int row = blockIdx.x;            // 0 .. 6143
    int d = (row >= G3) ? 1 : 0;
    int j = row - d * G3;

    const float4* wi = (const float4*)(wih + ((size_t)(l * 2 + d) * G3 + j) * E);
    const float4* wh = (const float4*)(whh + ((size_t)(l * 2 + d) * G3 + j) * H);
    const float4* xv = (l == 0)
        ? (const float4*)(table + (size_t)feat[0] * E)
        : (const float4*)g_x;
    const float4* hv = (const float4*)(hidden + (size_t)(2 * l + d) * H);

    int t = threadIdx.x;             // 0..63

    // Front-batch the full W_ih row (512 float4 over 64 threads = 8 each).
    float4 w[8], x[8], h[4];
    #pragma unroll
    for (int k = 0; k < 8; k++) w[k] = wi[t + k * 64];
    #pragma unroll
    for (int k = 0; k < 8; k++) x[k] = xv[t + k * 64];
    #pragma unroll
    for (int k = 0; k < 4; k++) h[k] = hv[t + k * 64];

    float si = 0.f;
    #pragma unroll
    for (int k = 0; k < 8; k++)
        si += w[k].x * x[k].x + w[k].y * x[k].y
            + w[k].z * x[k].z + w[k].w * x[k].w;

    // Block-wide zero test on the h-slice; skip W_hh traffic when zero.
    int nz = 0;
    #pragma unroll
    for (int k = 0; k < 4; k++)
        nz |= (h[k].x != 0.f) | (h[k].y != 0.f)
            | (h[k].z != 0.f) | (h[k].w != 0.f);
    int anynz = __syncthreads_or(nz);

    float sh = 0.f;
    if (anynz) {
        #pragma unroll
        for (int k = 0; k < 4; k++) {
            float4 u = wh[t + k * 64];
            sh += u.x * h[k].x + u.y * h[k].y + u.z * h[k].z + u.w * h[k].w;
        }
    }

    #pragma unroll
    for (int o = 16; o; o >>= 1) {
        si += __shfl_xor_sync(0xffffffffu, si, o);
        sh += __shfl_xor_sync(0xffffffffu, sh, o);
    }

    __shared__ float ri[2], rh[2];
    int warp = t >> 5, lane = t & 31;
    if (lane == 0) { ri[warp] = si; rh[warp] = sh; }
    __syncthreads();

    if (t == 0) {
        size_t boff = (size_t)(l * 2 + d) * G3 + j;
        g_gi[row] = ri[0] + ri[1] + bih[boff];
        g_gh[row] = rh[0] + rh[1] + bhh[boff];
    }
}

// ---------------------------------------------------------------------------
// Combine: GRU nonlinearity.  16 blocks x 128.
// ---------------------------------------------------------------------------
__global__ void __launch_bounds__(128) combine_kernel(
    const float* __restrict__ hidden, float* __restrict__ out, int l) {

    pdl_wait();

    int idx = blockIdx.x * 128 + threadIdx.x;    // 0 .. 2047
    int d = (idx >= H) ? 1 : 0;
    int j = idx - d * H;
    int base = d * G3;

    float ir  = g_gi[base + j],          hr = g_gh[base + j];
    float iz  = g_gi[base + H + j],      hz = g_gh[base + H + j];
    float in_ = g_gi[base + 2 * H + j],  hn = g_gh[base + 2 * H + j];

    float r = sigmoidf(ir + hr);
    float z = sigmoidf(iz + hz);
    float n = tanhf(in_ + r * hn);
    float hold = hidden[(size_t)(2 * l + d) * H + j];
    float hnew = (1.0f - z) * n + z * hold;

    g_x[idx] = hnew;                                  // next layer input
    out[OUTN + (size_t)(2 * l + d) * H + j] = hnew;   // new_hidden output
}

// ---------------------------------------------------------------------------
// FC: warp-per-row, 4 rows/block, 128 threads, x staged once per block.
// ---------------------------------------------------------------------------
__global__ void __launch_bounds__(128) fc_kernel(
    const float* __restrict__ fcw, const float* __restrict__ fcb,
    float* __restrict__ out) {

    pdl_wait();

    __shared__ __align__(16) float sx[E];
    int tid = threadIdx.x;
    for (int i = tid; i < E; i += 128) sx[i] = g_x[i];
    __syncthreads();

    int warp = tid >> 5, lane = tid & 31;
    int r = blockIdx.x * 4 + warp;
    if (r >= OUTN) return;

    const float4* wr = (const float4*)(fcw + (size_t)r * E);
    const float4* xv = (const float4*)sx;

    float sum = 0.f;
    #pragma unroll
    for (int k = 0; k < 16; k++) {
        float4 w = wr[lane + k * 32];
        float4 x = xv[lane + k * 32];
        sum += w.x * x.x + w.y * x.y + w.z * x.z + w.w * x.w;
    }
    #pragma unroll
    for (int o = 16; o; o >>= 1) sum += __shfl_xor_sync(0xffffffffu, sum, o);

    if (lane == 0) out[r] = sum + fcb[r];
}

// ---------------------------------------------------------------------------
// 9 launches: [gates(l), combine(l)] x4, fc — all PDL-attributed on the
// default stream.  Graph-capturable, allocation-free.
// ---------------------------------------------------------------------------
template <typename... Args>
static void launch_pdl(void (*kern)(Args...), dim3 grid, dim3 block,
                       Args... args) {
    cudaLaunchConfig_t cfg = {};
    cfg.gridDim = grid;
    cfg.blockDim = block;
    cudaLaunchAttribute attr[1];
    attr[0].id = cudaLaunchAttributeProgrammaticStreamSerialization;
    attr[0].val.programmaticStreamSerializationAllowed = 1;
    cfg.attrs = attr;
    cfg.numAttrs = 1;
    cudaLaunchKernelEx(&cfg, kern, args...);
}

extern "C" void kernel_launch(void* const* d_in, const int* in_sizes, int n_in,
                              void* d_out, int out_size) {
    const int*   feat   = (const int*)  d_in[0];
    const float* hidden = (const float*)d_in[1];
    const float* table  = (const float*)d_in[2];
    const float* wih    = (const float*)d_in[3];
    const float* whh    = (const float*)d_in[4];
    const float* bih    = (const float*)d_in[5];
    const float* bhh    = (const float*)d_in[6];
    const float* fcw    = (const float*)d_in[7];
    const float* fcb    = (const float*)d_in[8];
    float* out = (float*)d_out;

    for (int l = 0; l < NL; l++) {
        launch_pdl(gates_kernel, dim3(2 * G3), dim3(64),
                   wih, whh, bih, bhh, hidden, table, feat, l);
        launch_pdl(combine_kernel, dim3(16), dim3(128), hidden, out, l);
    }
    launch_pdl(fc_kernel, dim3((OUTN + 3) / 4), dim3(128), fcw, fcb, out);
}